// round 13
// baseline (speedup 1.0000x reference)
#include <cuda_runtime.h>

// SphericalHarmonics l<=3 (e3nn, 'integral' norm), unit-sphere normalized input.
// R4/R6/R10 (three different smem-staged store paths) all converge to ~47us,
// DRAM ~64%, L1 ~61% -> the smem round-trip keeps L1 busy either way.
// R9 (4-lane redundant, no smem) cut L1 to 42% but was issue-bound (55%).
// R11: the midpoint. TWO lanes per edge, each computes all 16 components
// (2x redundancy, cheap), each stores two ADJACENT float4s:
//   t = global tid, e = t>>1, p = t&1; stores outv[2t], outv[2t+1].
// Each warp's two STG.128 jointly fill every 128B line -> dense-ideal 16 wf
// per 16 edges. No smem, no barriers, no transpose. Stores use __stcs
// (streaming/evict-first): output is write-once, never re-read, and otherwise
// churns the 126MB L2 with a 256MB stream.

// K = 1/sqrt(4pi) folded into coefficients
#define C_K      0.2820947917738781f
#define C_KS3    0.4886025119029199f   // K*sqrt(3)
#define C_KS5    0.6307831305050401f   // K*sqrt(5)
#define C_KS15   1.0925484305920792f   // K*sqrt(15)
#define C_KS15H  0.5462742152960396f   // K*sqrt(15)/2
#define C_KS5H   0.31539156525252005f  // K*sqrt(5)/2
#define C_S7     2.6457513110645907f   // sqrt(7)      (on K-scaled sh2)
#define C_S42_6  1.0801234497346435f   // sqrt(42)/6   (on K-scaled sh2)
#define C_KS168  0.4570457994644658f   // K*sqrt(168)/8
#define C_KS7H   0.3731763325901154f   // K*sqrt(7)/2

#define NT 256

__global__ __launch_bounds__(NT) void sh_l3_kernel(
    const float* __restrict__ x, float4* __restrict__ outv, int n)
{
    const int t = blockIdx.x * NT + threadIdx.x;
    const int e = t >> 1;             // edge index (2 lanes share one edge)
    if (e >= n) return;
    const int p = t & 1;              // which half (quarters 0,1 vs 2,3)

    // 2-lane broadcast loads; warp spans 192 B per LDG -> 2 wavefronts
    float vx = __ldg(x + 3 * e + 0);
    float vy = __ldg(x + 3 * e + 1);
    float vz = __ldg(x + 3 * e + 2);

    float rinv = rsqrtf(vx * vx + vy * vy + vz * vz);
    vx *= rinv; vy *= rinv; vz *= rinv;

    float x2 = vx * vx;
    float y2 = vy * vy;
    float z2 = vz * vz;
    float x2z2 = x2 + z2;
    float p4y = 4.0f * y2 - x2z2;

    // l=1 (K folded)
    float o10 = C_KS3 * vx;
    float o11 = C_KS3 * vy;
    float o12 = C_KS3 * vz;
    // l=2 (K folded)
    float o20 = C_KS15 * vx * vz;
    float o21 = C_KS15 * vx * vy;
    float o22 = C_KS5 * y2 - C_KS5H * x2z2;
    float o23 = C_KS15 * vy * vz;
    float o24 = C_KS15H * (z2 - x2);
    // l=3 (recurrence on K-scaled l=2 -> already K-scaled)
    float o30 = C_S42_6 * (o20 * vz + o24 * vx);
    float o31 = C_S7 * o20 * vy;
    float o32 = C_KS168 * p4y * vx;
    float o33 = C_KS7H * vy * (2.0f * y2 - 3.0f * x2z2);
    float o34 = C_KS168 * vz * p4y;
    float o35 = C_S7 * o24 * vy;
    float o36 = C_S42_6 * (o24 * vz - o20 * vx);

    // Lane p stores quarters {2p, 2p+1} at float4 indices 2t and 2t+1.
    // (4e + 2p = 2t, so the warp's stores are dense by construction.)
    float4 r0 = p ? make_float4(o24, o30, o31, o32)
                  : make_float4(C_K, o10, o11, o12);
    float4 r1 = p ? make_float4(o33, o34, o35, o36)
                  : make_float4(o20, o21, o22, o23);

    // Streaming stores: write-once data, don't cache in L2.
    __stcs(outv + 2 * t,     r0);
    __stcs(outv + 2 * t + 1, r1);
}

extern "C" void kernel_launch(void* const* d_in, const int* in_sizes, int n_in,
                              void* d_out, int out_size) {
    const float* x = (const float*)d_in[0];
    float4* outv = (float4*)d_out;
    int n = in_sizes[0] / 3;          // x is [N, 3] float32
    long long threads_total = 2LL * n;
    int blocks = (int)((threads_total + NT - 1) / NT);
    sh_l3_kernel<<<blocks, NT>>>(x, outv, n);
}